// round 14
// baseline (speedup 1.0000x reference)
#include <cuda_runtime.h>
#include <cuda_fp16.h>
#include <cstdint>
#include <cstddef>

// ============================================================
// Problem constants
// ============================================================
#define N_TOK 8192
#define OUT_F 4096
#define IN_F  4096
#define NBITS 8
#define STEPF 0.0078125f

// GEMM tiling: 2 CTAs/SM x 128 threads, 64x64 warp tile, BK=64
#define BM 128
#define BN 128
#define BK 64
#define KTILES (IN_F / BK)      // 64
#define GTHREADS 128

// Stage layout (32KB): A 16KB | B 16KB  (128 rows x 128B swizzled)
#define OFF_B 16384
#define STAGE_BYTES 32768
#define SMEM_TOTAL  (2 * STAGE_BYTES)   // 65536 per CTA

// ============================================================
// Device scratch (allocation-free rule: __device__ globals)
// ============================================================
__device__ __align__(16) __half g_X[(size_t)N_TOK * IN_F];   // 64 MB
__device__ __align__(16) __half g_W[(size_t)OUT_F * IN_F];   // 32 MB

// ============================================================
// Helpers
// ============================================================
__device__ __forceinline__ uint32_t smem_u32(const void* p) {
    uint32_t a;
    asm("{ .reg .u64 t; cvta.to.shared.u64 t, %1; cvt.u32.u64 %0, t; }"
        : "=r"(a) : "l"(p));
    return a;
}

__device__ __forceinline__ void cp_async16(uint32_t saddr, const void* gaddr) {
    asm volatile("cp.async.cg.shared.global [%0], [%1], 16;"
                 :: "r"(saddr), "l"(gaddr));
}

__device__ __forceinline__ void ldmatrix_x4(uint32_t& r0, uint32_t& r1,
                                            uint32_t& r2, uint32_t& r3,
                                            uint32_t addr) {
    asm volatile("ldmatrix.sync.aligned.m8n8.x4.shared.b16 {%0,%1,%2,%3}, [%4];"
                 : "=r"(r0), "=r"(r1), "=r"(r2), "=r"(r3) : "r"(addr));
}

__device__ __forceinline__ void mma_16816(float& d0, float& d1, float& d2, float& d3,
                                          uint32_t a0, uint32_t a1, uint32_t a2, uint32_t a3,
                                          uint32_t b0, uint32_t b1) {
    asm volatile(
        "mma.sync.aligned.m16n8k16.row.col.f32.f16.f16.f32 "
        "{%0,%1,%2,%3}, {%4,%5,%6,%7}, {%8,%9}, {%0,%1,%2,%3};"
        : "+f"(d0), "+f"(d1), "+f"(d2), "+f"(d3)
        : "r"(a0), "r"(a1), "r"(a2), "r"(a3), "r"(b0), "r"(b1));
}

// ============================================================
// Fused prep kernel (exact R10 version — empirically best)
// ============================================================
#define WBLOCKS 32768   // (OUT_F*IN_F/2) / 256
#define XBLOCKS 32768   // (N_TOK*IN_F/4) / 256

__global__ void prep_kernel(const float* __restrict__ x,
                            const float* __restrict__ w_twos,
                            const float* __restrict__ base) {
    if (blockIdx.x < WBLOCKS) {
        size_t p = (size_t)blockIdx.x * blockDim.x + threadIdx.x;

        float bs[NBITS];
#pragma unroll
        for (int j = 0; j < NBITS; j++) bs[j] = __ldg(base + j);

        const float4* src = reinterpret_cast<const float4*>(w_twos + p * 2 * NBITS);
        float4 a0 = src[0], a1 = src[1], a2 = src[2], a3 = src[3];

        float w0 = a0.x * bs[0] + a0.y * bs[1] + a0.z * bs[2] + a0.w * bs[3] +
                   a1.x * bs[4] + a1.y * bs[5] + a1.z * bs[6] + a1.w * bs[7];
        float w1 = a2.x * bs[0] + a2.y * bs[1] + a2.z * bs[2] + a2.w * bs[3] +
                   a3.x * bs[4] + a3.y * bs[5] + a3.z * bs[6] + a3.w * bs[7];

        __half2 h = __floats2half2_rn(w0 * STEPF, w1 * STEPF);
        reinterpret_cast<uint32_t*>(g_W)[p] = *reinterpret_cast<uint32_t*>(&h);
    } else {
        size_t i = (size_t)(blockIdx.x - WBLOCKS) * blockDim.x + threadIdx.x;
        float4 v = reinterpret_cast<const float4*>(x)[i];
        __half2 h01 = __floats2half2_rn(v.x, v.y);
        __half2 h23 = __floats2half2_rn(v.z, v.w);
        uint2 pk;
        pk.x = *reinterpret_cast<uint32_t*>(&h01);
        pk.y = *reinterpret_cast<uint32_t*>(&h23);
        reinterpret_cast<uint2*>(g_X)[i] = pk;
    }
}

// ============================================================
// fp16 mma.sync GEMM  out[m,n] = sum_k X[m,k]*W[n,k] + b[n]
// BM=128, BN=128, BK=64, 4 warps (2m x 2n, warp tile 64x64),
// 2-stage ring, 2 CTAs/SM (independent barrier domains),
// drip-fed cp.async, tail wait, cross-tile ks0 prefetch.
// ============================================================
__global__ __launch_bounds__(GTHREADS, 2)
void gemm_kernel(const float* __restrict__ bias, float* __restrict__ out) {
    extern __shared__ char sm[];
    const uint32_t smem_base = smem_u32(sm);
    const int tid  = threadIdx.x;
    const int wid  = tid >> 5;     // 0..3
    const int lane = tid & 31;
    const int warp_m = wid & 1;    // 64 rows each
    const int warp_n = wid >> 1;   // 0..1, 64 cols each
    const int m0 = blockIdx.y * BM;
    const int n0 = blockIdx.x * BN;

    // ---- per-lane ldmatrix addressing ----
    uint32_t a_row[4], a_xor[4];
#pragma unroll
    for (int im = 0; im < 4; ++im) {
        int r = warp_m * 64 + im * 16 + (lane & 15);
        a_row[im] = (uint32_t)(r * 128);
        a_xor[im] = (uint32_t)((r & 7) * 16);
    }
    const uint32_t a_khb = (uint32_t)((lane >> 4) * 16);

    uint32_t b_row[4], b_xor[4];
#pragma unroll
    for (int jp = 0; jp < 4; ++jp) {
        int r = warp_n * 64 + jp * 16 + ((lane >> 4) * 8) + (lane & 7);
        b_row[jp] = (uint32_t)(OFF_B + r * 128);
        b_xor[jp] = (uint32_t)((r & 7) * 16);
    }
    const uint32_t b_khb = (uint32_t)(((lane >> 3) & 1) * 16);

    // ---- cp.async addressing: base + stride (saves registers) ----
    // 1024 16B chunks per operand tile, 8 per thread; chunk i at
    // row cr + 16*i (row-step keeps swizzle xor invariant: 16 % 8 == 0).
    const int cr = tid >> 3, cc = tid & 7;
    const uint32_t soff0 = (uint32_t)(cr * 128 + ((cc * 16) ^ ((cr & 7) * 16)));
    const __half* a_g0 = g_X + (size_t)(m0 + cr) * IN_F + cc * 8;
    const __half* b_g0 = g_W + (size_t)(n0 + cr) * IN_F + cc * 8;

    float acc[4][8][4];   // 128 regs: warp tile 64x64
#pragma unroll
    for (int im = 0; im < 4; ++im)
#pragma unroll
        for (int jn = 0; jn < 8; ++jn)
#pragma unroll
            for (int q = 0; q < 4; ++q) acc[im][jn][q] = 0.0f;

    // ---- prologue: load tile 0 into stage 0 ----
#pragma unroll
    for (int i = 0; i < 8; ++i)
        cp_async16(smem_base + soff0 + i * 2048,
                   a_g0 + (size_t)(i * 16) * IN_F);
#pragma unroll
    for (int i = 0; i < 8; ++i)
        cp_async16(smem_base + OFF_B + soff0 + i * 2048,
                   b_g0 + (size_t)(i * 16) * IN_F);
    asm volatile("cp.async.commit_group;");
    asm volatile("cp.async.wait_group 0;");
    __syncthreads();

    uint32_t a[4][4];   // single-buffer fragments
    uint32_t b[8][2];

    // prefetch ks0 frags of tile 0
    {
        uint32_t sS = smem_base;
#pragma unroll
        for (int im = 0; im < 4; ++im)
            ldmatrix_x4(a[im][0], a[im][1], a[im][2], a[im][3],
                        sS + a_row[im] + (a_khb ^ a_xor[im]));
#pragma unroll
        for (int jp = 0; jp < 4; ++jp)
            ldmatrix_x4(b[2 * jp][0], b[2 * jp][1],
                        b[2 * jp + 1][0], b[2 * jp + 1][1],
                        sS + b_row[jp] + (b_khb ^ b_xor[jp]));
    }

    // ---- main loop: 64 K-tiles, tail barrier per tile ----
    for (int kt = 0; kt < KTILES; ++kt) {
        const uint32_t sS = smem_base + (kt & 1) * STAGE_BYTES;
        const uint32_t sb = smem_base + ((kt + 1) & 1) * STAGE_BYTES;
        const int ktn = kt + 1;
        const int kof = ktn * BK;

#pragma unroll
        for (int ks = 0; ks < 4; ++ks) {
            // frag loads for this ks (ks0 was prefetched across the barrier)
            if (ks > 0) {
                const uint32_t k32 = (uint32_t)(ks * 32);
#pragma unroll
                for (int im = 0; im < 4; ++im)
                    ldmatrix_x4(a[im][0], a[im][1], a[im][2], a[im][3],
                                sS + a_row[im] + ((k32 + a_khb) ^ a_xor[im]));
#pragma unroll
                for (int jp = 0; jp < 4; ++jp)
                    ldmatrix_x4(b[2 * jp][0], b[2 * jp][1],
                                b[2 * jp + 1][0], b[2 * jp + 1][1],
                                sS + b_row[jp] + ((k32 + b_khb) ^ b_xor[jp]));
            }
#pragma unroll
            for (int im = 0; im < 4; ++im)
#pragma unroll
                for (int jn = 0; jn < 8; ++jn)
                    mma_16816(acc[im][jn][0], acc[im][jn][1],
                              acc[im][jn][2], acc[im][jn][3],
                              a[im][0], a[im][1], a[im][2], a[im][3],
                              b[jn][0], b[jn][1]);

            // drip-feed next tile's copies under the tensor work
            if (ktn < KTILES) {
                if (ks == 0) {
#pragma unroll
                    for (int i = 0; i < 8; ++i)
                        cp_async16(sb + soff0 + i * 2048,
                                   a_g0 + kof + (size_t)(i * 16) * IN_F);
                } else if (ks == 1) {
#pragma unroll
                    for (int i = 0; i < 8; ++i)
                        cp_async16(sb + OFF_B + soff0 + i * 2048,
                                   b_g0 + kof + (size_t)(i * 16) * IN_F);
                }
            }
            if (ks == 1) asm volatile("cp.async.commit_group;");
        }

        // tail rendezvous: next tile's copies complete, publish, flip stages
        asm volatile("cp.async.wait_group 0;");
        __syncthreads();

        // cross-tile prefetch: ks0 frags of tile kt+1 from the other stage
        if (ktn < KTILES) {
#pragma unroll
            for (int im = 0; im < 4; ++im)
                ldmatrix_x4(a[im][0], a[im][1], a[im][2], a[im][3],
                            sb + a_row[im] + (a_khb ^ a_xor[im]));
#pragma unroll
            for (int jp = 0; jp < 4; ++jp)
                ldmatrix_x4(b[2 * jp][0], b[2 * jp][1],
                            b[2 * jp + 1][0], b[2 * jp + 1][1],
                            sb + b_row[jp] + (b_khb ^ b_xor[jp]));
        }
    }

    // ---- epilogue: bias + store ----
#pragma unroll
    for (int im = 0; im < 4; ++im) {
        int r0 = m0 + warp_m * 64 + im * 16 + (lane >> 2);
        int r1 = r0 + 8;
#pragma unroll
        for (int jn = 0; jn < 8; ++jn) {
            int c = n0 + warp_n * 64 + jn * 8 + (lane & 3) * 2;
            float2 bv = *reinterpret_cast<const float2*>(bias + c);
            float2 o0, o1;
            o0.x = acc[im][jn][0] + bv.x;
            o0.y = acc[im][jn][1] + bv.y;
            o1.x = acc[im][jn][2] + bv.x;
            o1.y = acc[im][jn][3] + bv.y;
            *reinterpret_cast<float2*>(out + (size_t)r0 * OUT_F + c) = o0;
            *reinterpret_cast<float2*>(out + (size_t)r1 * OUT_F + c) = o1;
        }
    }
}

// ============================================================
// Host launcher
// ============================================================
extern "C" void kernel_launch(void* const* d_in, const int* in_sizes, int n_in,
                              void* d_out, int out_size) {
    const float* x      = (const float*)d_in[0];
    const float* w_twos = (const float*)d_in[1];
    const float* b      = (const float*)d_in[2];
    const float* base   = (const float*)d_in[3];
    float* out = (float*)d_out;

    cudaFuncSetAttribute(gemm_kernel,
                         cudaFuncAttributeMaxDynamicSharedMemorySize, SMEM_TOTAL);

    prep_kernel<<<WBLOCKS + XBLOCKS, 256>>>(x, w_twos, base);

    dim3 grid(OUT_F / BN, N_TOK / BM);
    gemm_kernel<<<grid, GTHREADS, SMEM_TOTAL>>>(b, out);
}